// round 10
// baseline (speedup 1.0000x reference)
#include <cuda_runtime.h>
#include <math.h>

#define B    16
#define D    2048
#define T    100
#define N0   4096
#define N1   4096
#define N2   2048
#define NCLS 10

constexpr float DECAY = 0.9f;
constexpr float THRESH = 1.0f;
constexpr float LR = 0.01f;
constexpr float TRD = 0.95f;

#define TIA 128
#define TIB 128
#define JBA (N1 / 256)          // 16 j-blocks for Wa
#define JBB (N2 / 256)          // 8  j-blocks for Wb
#define NBA (JBA * (N0 / TIA))  // 512 wa tiles
#define NBB (JBB * (N1 / TIB))  // 256 wb tiles
#define GRIDP 592               // persistent grid (4 blocks/SM * 148 SMs)

// ---------------- device state (per-neuron state in [j][b] layout, b fast) ----------------
__device__ float g_Wa[(size_t)N0 * N1];           // 64 MB
__device__ float g_Wb[(size_t)N1 * N2];           // 32 MB
__device__ float g_s0f[(size_t)(T + 1) * N0 * B];
__device__ float g_p0f[(size_t)(T + 1) * N0 * B];
__device__ float g_s1f[2][N1 * B];
__device__ float g_s2f[N2 * B];
__device__ float g_q0n[N1 * B];
__device__ float g_q1n[N2 * B];
__device__ float g_p1[N1 * B];
__device__ float g_V1[N1 * B];
__device__ float g_V2[N2 * B];
__device__ int   g_r1[N1 * B];
__device__ int   g_r2[N2 * B];
__device__ float g_cur1[N1 * B];                  // [j][b]
__device__ float g_cur2[N2 * B];                  // [j][b]
__device__ float g_cnt[N2 * B];                   // [j][b]
__device__ float g_racc[B * N0];
__device__ unsigned g_task[T + 1];                // per-step dynamic task counters
__device__ unsigned g_barctr;                     // monotonic grid barrier counter

// ---------------- helpers ----------------
typedef unsigned long long u64;
union F4U { float4 f4; u64 u[2]; };
__device__ __forceinline__ u64 pack2(float lo, float hi) {
    u64 r; asm("mov.b64 %0, {%1,%2};" : "=l"(r) : "f"(lo), "f"(hi)); return r;
}
__device__ __forceinline__ void unpack2(u64 v, float& lo, float& hi) {
    asm("mov.b64 {%0,%1}, %2;" : "=f"(lo), "=f"(hi) : "l"(v));
}
__device__ __forceinline__ void fma2(u64& acc, u64 a, u64 b) {
    asm("fma.rn.f32x2 %0, %1, %2, %0;" : "+l"(acc) : "l"(a), "l"(b));
}
__device__ __forceinline__ u64 add2(u64 a, u64 b) {
    u64 r; asm("add.rn.f32x2 %0, %1, %2;" : "=l"(r) : "l"(a), "l"(b)); return r;
}
__device__ __forceinline__ void load16_cg(const float* p, u64* dst) {
    const float4* p4 = (const float4*)p;
    F4U v;
#pragma unroll
    for (int q = 0; q < 4; q++) {
        v.f4 = __ldcg(p4 + q);
        dst[2 * q] = v.u[0]; dst[2 * q + 1] = v.u[1];
    }
}
__device__ __forceinline__ unsigned smem_u32(const void* p) {
    return (unsigned)__cvta_generic_to_shared(p);
}
__device__ __forceinline__ void cpa16(unsigned sdst, const float4* gsrc) {
    asm volatile("cp.async.cg.shared.global [%0], [%1], 16;" :: "r"(sdst), "l"(gsrc));
}
__device__ __forceinline__ void cpcommit() {
    asm volatile("cp.async.commit_group;" ::: "memory");
}
__device__ __forceinline__ void red4(float* addr, float a, float b, float c, float d) {
    asm volatile("red.global.add.v4.f32 [%0], {%1, %2, %3, %4};"
                 :: "l"(addr), "f"(a), "f"(b), "f"(c), "f"(d) : "memory");
}

// ---------------- grid barrier (all GRIDP blocks co-resident) ----------------
__device__ __forceinline__ void gridbar(unsigned& phase) {
    phase += GRIDP;
    __threadfence();
    __syncthreads();
    if (threadIdx.x == 0) {
        atomicAdd(&g_barctr, 1u);
        while (*((volatile unsigned*)&g_barctr) < phase) __nanosleep(32);
    }
    __syncthreads();
}

// ---------------- W-pass: cooperatively cg-staged weights + fused STDP + GEMM ----------------
// RACE FIX vs R8: cp.async completion is per-thread; cooperative staging requires
// __syncthreads() after wait_group (before consuming other threads' copies) and
// before prefetching into a buffer other threads may still be reading.
template<int TI, int NJ>
__device__ __forceinline__ void wpass(
    int jb, int ib,
    float* __restrict__ W,
    const float* __restrict__ rowP,
    const float* __restrict__ rowS,
    const float* __restrict__ rowC,
    const float* __restrict__ colS,
    const float* __restrict__ colQ,
    float* __restrict__ cur,         // [j][b]
    float4* sh,                      // TI*12 float4 row broadcast (reused for epilogue)
    float2* wsh)                     // 2 * 8 * 128 float2 weight stage
{
    const int tid = threadIdx.x;
    const int j0 = jb * 256 + tid * 2;
    const int i0 = ib * TI;
    constexpr int RS = NJ / 2;       // row stride in float2
    constexpr int RS4 = NJ / 4;      // row stride in float4
    constexpr int C = TI / 8;        // chunks

    const float4* blk4 = (const float4*)W + (size_t)i0 * RS4 + jb * 64;
    float2* wgl = (float2*)W + (size_t)i0 * RS + jb * 128 + tid;
    unsigned sbase = smem_u32(wsh);

    // stage chunks 0 and 1 (16B cp.async.cg, L1-bypassing, coalesced)
#pragma unroll
    for (int cc = 0; cc < 2; cc++) {
        unsigned sd = sbase + cc * 8192;
        const float4* gb = blk4 + (size_t)(cc * 8) * RS4;
#pragma unroll
        for (int kk = 0; kk < 4; kk++) {
            int idx = kk * 128 + tid;
            cpa16(sd + idx * 16, gb + (size_t)(idx >> 6) * RS4 + (idx & 63));
        }
        cpcommit();
    }

    u64 sA[8], sB[8], qA[8], qB[8], aA[8], aB[8];
    load16_cg(colS + (size_t)j0 * B, sA);
    load16_cg(colS + (size_t)(j0 + 1) * B, sB);
    load16_cg(colQ + (size_t)j0 * B, qA);
    load16_cg(colQ + (size_t)(j0 + 1) * B, qB);
#pragma unroll
    for (int g = 0; g < 8; g++) { aA[g] = 0ull; aB[g] = 0ull; }

    {
        const float4* a0 = (const float4*)(rowP + (size_t)i0 * B);
        const float4* a1 = (const float4*)(rowS + (size_t)i0 * B);
        const float4* a2 = (const float4*)(rowC + (size_t)i0 * B);
#pragma unroll
        for (int k = tid; k < TI * 4; k += 128) {
            sh[k] = __ldcg(a0 + k); sh[TI * 4 + k] = __ldcg(a1 + k); sh[TI * 8 + k] = __ldcg(a2 + k);
        }
    }
    __syncthreads();

    const F4U* p4 = (const F4U*)sh;
    const F4U* s4 = (const F4U*)(sh + TI * 4);
    const F4U* c4 = (const F4U*)(sh + TI * 8);

    for (int c = 0; c < C; c++) {
        if (c + 1 < C) asm volatile("cp.async.wait_group 1;" ::: "memory");
        else           asm volatile("cp.async.wait_group 0;" ::: "memory");
        __syncthreads();   // ALL threads' copies for chunk c complete -> chunk visible
        const float2* wsrc = wsh + (c & 1) * 1024 + tid;
#pragma unroll 2
        for (int k = 0; k < 8; k++) {
            int r = c * 8 + k;
            float2 w = wsrc[k * 128];
            u64 dA0 = 0ull, dA1 = 0ull, dB0 = 0ull, dB1 = 0ull;
            F4U v;
#pragma unroll
            for (int g = 0; g < 4; g++) {
                v = p4[r * 4 + g];
                fma2(dA0, v.u[0], sA[2 * g]); fma2(dA1, v.u[1], sA[2 * g + 1]);
                fma2(dB0, v.u[0], sB[2 * g]); fma2(dB1, v.u[1], sB[2 * g + 1]);
            }
#pragma unroll
            for (int g = 0; g < 4; g++) {
                v = s4[r * 4 + g];
                fma2(dA0, v.u[0], qA[2 * g]); fma2(dA1, v.u[1], qA[2 * g + 1]);
                fma2(dB0, v.u[0], qB[2 * g]); fma2(dB1, v.u[1], qB[2 * g + 1]);
            }
            u64 eA = add2(dA0, dA1), eB = add2(dB0, dB1);
            float la, ha, lb, hb;
            unpack2(eA, la, ha); unpack2(eB, lb, hb);
            float nwa = fminf(1.f, fmaxf(-1.f, fmaf(LR, la + ha, w.x)));
            float nwb = fminf(1.f, fmaxf(-1.f, fmaf(LR, lb + hb, w.y)));
            float2 nw; nw.x = nwa; nw.y = nwb;
            wgl[(size_t)r * RS] = nw;
            u64 wa2 = pack2(nwa, nwa), wb2 = pack2(nwb, nwb);
#pragma unroll
            for (int g = 0; g < 4; g++) {
                v = c4[r * 4 + g];
                fma2(aA[2 * g], v.u[0], wa2); fma2(aA[2 * g + 1], v.u[1], wa2);
                fma2(aB[2 * g], v.u[0], wb2); fma2(aB[2 * g + 1], v.u[1], wb2);
            }
        }
        if (c + 2 < C) {
            __syncthreads();   // no thread still reading buffer parity (c&1)
            unsigned sd = sbase + (c & 1) * 8192;
            const float4* gb = blk4 + (size_t)((c + 2) * 8) * RS4;
#pragma unroll
            for (int kk = 0; kk < 4; kk++) {
                int idx = kk * 128 + tid;
                cpa16(sd + idx * 16, gb + (size_t)(idx >> 6) * RS4 + (idx & 63));
            }
            cpcommit();
        }
    }

    // ---- coalesced reduction epilogue via smem transpose (reuses sh: 256*17 floats) ----
    __syncthreads();
    float* sT = (float*)sh;
    {
        int lj = tid * 2;
#pragma unroll
        for (int g = 0; g < 8; g++) {
            float lo, hi;
            unpack2(aA[g], lo, hi);
            sT[lj * 17 + 2 * g] = lo; sT[lj * 17 + 2 * g + 1] = hi;
            unpack2(aB[g], lo, hi);
            sT[(lj + 1) * 17 + 2 * g] = lo; sT[(lj + 1) * 17 + 2 * g + 1] = hi;
        }
    }
    __syncthreads();
    {
        float* curb = cur + (size_t)jb * 256 * B;
#pragma unroll
        for (int k = 0; k < 8; k++) {
            int gi = k * 512 + tid * 4;
            int j = gi >> 4, b = gi & 15;
            const float* sp = sT + j * 17 + b;
            red4(curb + gi, sp[0], sp[1], sp[2], sp[3]);
        }
    }
    __syncthreads();   // protect sT before next tile re-stages sh
}

// ---------------- lif body (element g in [j][b] flat index) ----------------
__device__ __forceinline__ void lif_body(int t, int g) {
    // lif1(t)
    float cur = __ldcg(&g_cur1[g]);
    g_cur1[g] = 0.f;
    float V = DECAY * g_V1[g] + cur;
    int refr = g_r1[g];
    bool spk = (V > THRESH) && (refr <= 0);
    float s = spk ? 1.f : 0.f;
    g_V1[g] = spk ? 0.f : V;
    g_r1[g] = spk ? 2 : (refr > 0 ? refr - 1 : 0);
    g_s1f[t & 1][g] = s;
    g_q0n[g] = TRD * g_q0n[g] - s;
    // lif2(t-1)
    if (t > 0) {
        float s1m = g_s1f[(t & 1) ^ 1][g];
        g_p1[g] = TRD * g_p1[g] + s1m;
        if (g < N2 * B) {
            float c2 = __ldcg(&g_cur2[g]);
            g_cur2[g] = 0.f;
            float V2 = DECAY * g_V2[g] + c2;
            int r2 = g_r2[g];
            bool sp2 = (V2 > THRESH) && (r2 <= 0);
            float s2 = sp2 ? 1.f : 0.f;
            g_V2[g] = sp2 ? 0.f : V2;
            g_r2[g] = sp2 ? 2 : (r2 > 0 ? r2 - 1 : 0);
            g_cnt[g] += s2;
            g_s2f[g] = s2;
            g_q1n[g] = TRD * g_q1n[g] - s2;
        }
    }
}

// ---------------- persistent kernel: whole T loop ----------------
__global__ __launch_bounds__(128, 4) void k_step() {
    __shared__ float4 sh[TIA * 12];       // 24 KB
    __shared__ float2 wsh[2 * 8 * 128];   // 16 KB
    __shared__ int s_task;
    unsigned phase = 0;

    for (int t = -1; t < T; t++) {
        int ta = t + 1;
        bool hasWa = (ta < T), hasWb = (t >= 0);
        int ntasks = (hasWa ? NBA : 0) + (hasWb ? NBB : 0);
        int wbbase = hasWa ? NBA : 0;
        // ---- wab phase: dynamic tasking ----
        for (;;) {
            if (threadIdx.x == 0) s_task = (int)atomicAdd(&g_task[ta], 1u);
            __syncthreads();
            int task = s_task;
            __syncthreads();
            if (task >= ntasks) break;
            if (hasWa && task < NBA) {
                size_t base = (size_t)ta * N0 * B;
                wpass<TIA, N1>(task % JBA, task / JBA, g_Wa,
                               g_p0f + base, g_s0f + base, g_s0f + base + (size_t)N0 * B,
                               g_s1f[(ta & 1) ^ 1], g_q0n, g_cur1, sh, wsh);
            } else {
                int tile = task - wbbase;
                wpass<TIB, N2>(tile % JBB, tile / JBB, g_Wb,
                               g_p1, g_s1f[(t & 1) ^ 1], g_s1f[t & 1],
                               g_s2f, g_q1n, g_cur2, sh, wsh);
            }
        }
        // ---- lif phase ----
        if (ta < T) {
            gridbar(phase);
            int g = blockIdx.x * 128 + threadIdx.x;
            if (g < N1 * B) lif_body(ta, g);
            gridbar(phase);
        }
    }
}

// ---------------- init ----------------
__global__ void k_init() {
    int i = blockIdx.x * blockDim.x + threadIdx.x;
    int n = gridDim.x * blockDim.x;
    if (i == 0) g_barctr = 0;
    for (int k = i; k <= T; k += n) g_task[k] = 0;
    for (int k = i; k < N0 * B; k += n) { g_s0f[k] = 0.f; g_p0f[k] = 0.f; g_racc[k] = 0.f; }
    for (int k = i; k < N1 * B; k += n) {
        g_s1f[0][k] = 0.f; g_s1f[1][k] = 0.f; g_q0n[k] = 0.f; g_p1[k] = 0.f;
        g_V1[k] = 0.f; g_r1[k] = 0; g_cur1[k] = 0.f;
    }
    for (int k = i; k < N2 * B; k += n) {
        g_s2f[k] = 0.f; g_q1n[k] = 0.f; g_V2[k] = 0.f; g_r2[k] = 0;
        g_cur2[k] = 0.f; g_cnt[k] = 0.f;
    }
}

// ---------------- encoder GEMM ----------------
__global__ void k_enc(const float* __restrict__ x, const float* __restrict__ Wenc) {
    __shared__ float xs[B][128];
    int i = blockIdx.x * 128 + threadIdx.x;
    int d0 = blockIdx.y * 128;
    for (int k = threadIdx.x; k < B * 128; k += 128) {
        int b = k / 128, dl = k % 128;
        xs[b][dl] = x[b * D + d0 + dl];
    }
    __syncthreads();
    float acc[B];
#pragma unroll
    for (int b = 0; b < B; b++) acc[b] = 0.f;
    for (int dl = 0; dl < 128; dl++) {
        float w = Wenc[(size_t)(d0 + dl) * N0 + i];
#pragma unroll
        for (int b = 0; b < B; b++) acc[b] = fmaf(xs[b][dl], w, acc[b]);
    }
#pragma unroll
    for (int b = 0; b < B; b++) atomicAdd(&g_racc[b * N0 + i], acc[b]);
}

// ---------------- precompute s0/p0 ----------------
__global__ void k_pre(const float* __restrict__ u, const float* __restrict__ benc) {
    int idx = blockIdx.x * blockDim.x + threadIdx.x;
    int i = idx & (N0 - 1), b = idx >> 12;
    float rate = 1.f / (1.f + expf(-(g_racc[b * N0 + i] + benc[i])));
    float V = 0.f, p = 0.f;
    int refr = 0;
    const float* up = u + (size_t)b * T * N0 + i;
    for (int t = 0; t < T; t++) {
        float s_in = (up[(size_t)t * N0] < rate) ? 1.f : 0.f;
        V = DECAY * V + s_in;
        bool spk = (V > THRESH) && (refr <= 0);
        float s = spk ? 1.f : 0.f;
        V = spk ? 0.f : V;
        refr = spk ? 2 : (refr > 0 ? refr - 1 : 0);
        p = TRD * p + s;
        size_t o = (size_t)(t + 1) * N0 * B + (size_t)i * B + b;
        g_s0f[o] = s;
        g_p0f[o] = p;
    }
}

// ---------------- final lif2 (step T-1) ----------------
__global__ void k_lif2fin() {
    int tid = blockIdx.x * blockDim.x + threadIdx.x;
    float c2 = g_cur2[tid];
    float V2 = DECAY * g_V2[tid] + c2;
    int r2 = g_r2[tid];
    bool sp2 = (V2 > THRESH) && (r2 <= 0);
    g_cnt[tid] += sp2 ? 1.f : 0.f;
}

// ---------------- readout ----------------
__global__ void k_out(const float* __restrict__ Wdec, const float* __restrict__ bdec,
                      float* __restrict__ out) {
    int b = blockIdx.x;
    int tid = threadIdx.x;
    int lane = tid & 31, wid = tid >> 5;
    float a[NCLS];
#pragma unroll
    for (int c = 0; c < NCLS; c++) a[c] = 0.f;
    for (int k = tid; k < N2; k += 256) {
        float cv = g_cnt[k * B + b];
#pragma unroll
        for (int c = 0; c < NCLS; c++) a[c] = fmaf(cv, Wdec[k * NCLS + c], a[c]);
    }
#pragma unroll
    for (int c = 0; c < NCLS; c++)
#pragma unroll
        for (int o = 16; o > 0; o >>= 1)
            a[c] += __shfl_xor_sync(0xffffffffu, a[c], o);
    __shared__ float sred[8][NCLS];
    if (lane == 0)
#pragma unroll
        for (int c = 0; c < NCLS; c++) sred[wid][c] = a[c];
    __syncthreads();
    if (tid < NCLS) {
        float s = bdec[tid];
#pragma unroll
        for (int w = 0; w < 8; w++) s += sred[w][tid];
        out[b * NCLS + tid] = s;
    }
}

// ---------------- launch ----------------
extern "C" void kernel_launch(void* const* d_in, const int* in_sizes, int n_in,
                              void* d_out, int out_size) {
    (void)in_sizes; (void)n_in; (void)out_size;
    const float* x    = (const float*)d_in[0];
    const float* u    = (const float*)d_in[1];
    const float* Wenc = (const float*)d_in[2];
    const float* benc = (const float*)d_in[3];
    const float* W0   = (const float*)d_in[4];
    const float* W1   = (const float*)d_in[5];
    const float* Wdec = (const float*)d_in[6];
    const float* bdec = (const float*)d_in[7];
    float* out = (float*)d_out;

    cudaMemcpyToSymbolAsync(g_Wa, W0, sizeof(float) * (size_t)N0 * N1, 0,
                            cudaMemcpyDeviceToDevice, 0);
    cudaMemcpyToSymbolAsync(g_Wb, W1, sizeof(float) * (size_t)N1 * N2, 0,
                            cudaMemcpyDeviceToDevice, 0);
    k_init<<<256, 256>>>();
    k_enc<<<dim3(N0 / 128, D / 128), 128>>>(x, Wenc);
    k_pre<<<(N0 * B) / 256, 256>>>(u, benc);
    k_step<<<GRIDP, 128>>>();
    k_lif2fin<<<(N2 * B) / 256, 256>>>();
    k_out<<<B, 256>>>(Wdec, bdec, out);
}

// round 14
// speedup vs baseline: 1.0726x; 1.0726x over previous
#include <cuda_runtime.h>
#include <math.h>

#define B    16
#define D    2048
#define T    100
#define N0   4096
#define N1   4096
#define N2   2048
#define NCLS 10

constexpr float DECAY = 0.9f;
constexpr float THRESH = 1.0f;
constexpr float LR = 0.01f;
constexpr float TRD = 0.95f;

#define TIA 128
#define TIB 128
#define JBA (N1 / 256)          // 16 j-blocks for Wa
#define JBB (N2 / 256)          // 8  j-blocks for Wb
#define NBA (JBA * (N0 / TIA))  // 512 wa tiles
#define NBB (JBB * (N1 / TIB))  // 256 wb tiles

// ---------------- device state (per-neuron state in [j][b] layout, b fast) ----------------
__device__ float g_Wa[(size_t)N0 * N1];           // 64 MB
__device__ float g_Wb[(size_t)N1 * N2];           // 32 MB
__device__ float g_s0f[(size_t)(T + 1) * N0 * B];
__device__ float g_p0f[(size_t)(T + 1) * N0 * B];
__device__ float g_s1f[2][N1 * B];
__device__ float g_s2f[N2 * B];
__device__ float g_q0n[N1 * B];
__device__ float g_q1n[N2 * B];
__device__ float g_p1[N1 * B];
__device__ float g_V1[N1 * B];
__device__ float g_V2[N2 * B];
__device__ int   g_r1[N1 * B];
__device__ int   g_r2[N2 * B];
__device__ float g_cur1[N1 * B];                  // [j][b]
__device__ float g_cur2[N2 * B];                  // [j][b]
__device__ float g_cnt[N2 * B];                   // [j][b]
__device__ float g_racc[B * N0];

// ---------------- helpers ----------------
typedef unsigned long long u64;
union F4U { float4 f4; u64 u[2]; };
__device__ __forceinline__ u64 pack2(float lo, float hi) {
    u64 r; asm("mov.b64 %0, {%1,%2};" : "=l"(r) : "f"(lo), "f"(hi)); return r;
}
__device__ __forceinline__ void unpack2(u64 v, float& lo, float& hi) {
    asm("mov.b64 {%0,%1}, %2;" : "=f"(lo), "=f"(hi) : "l"(v));
}
__device__ __forceinline__ void fma2(u64& acc, u64 a, u64 b) {
    asm("fma.rn.f32x2 %0, %1, %2, %0;" : "+l"(acc) : "l"(a), "l"(b));
}
__device__ __forceinline__ u64 add2(u64 a, u64 b) {
    u64 r; asm("add.rn.f32x2 %0, %1, %2;" : "=l"(r) : "l"(a), "l"(b)); return r;
}
__device__ __forceinline__ void load16(const float* p, u64* dst) {
    const float4* p4 = (const float4*)p;
    F4U v;
#pragma unroll
    for (int q = 0; q < 4; q++) {
        v.f4 = p4[q];
        dst[2 * q] = v.u[0]; dst[2 * q + 1] = v.u[1];
    }
}
__device__ __forceinline__ unsigned smem_u32(const void* p) {
    return (unsigned)__cvta_generic_to_shared(p);
}
__device__ __forceinline__ void cpa8(unsigned sdst, const float2* gsrc) {
    asm volatile("cp.async.ca.shared.global [%0], [%1], 8;" :: "r"(sdst), "l"(gsrc));
}
__device__ __forceinline__ void cpcommit() {
    asm volatile("cp.async.commit_group;" ::: "memory");
}
__device__ __forceinline__ void red4(float* addr, float a, float b, float c, float d) {
    asm volatile("red.global.add.v4.f32 [%0], {%1, %2, %3, %4};"
                 :: "l"(addr), "f"(a), "f"(b), "f"(c), "f"(d) : "memory");
}

// ---------------- W-pass: per-thread cp.async-staged weights + fused STDP + GEMM ----------------
// Thread owns adjacent columns (j0, j0+1). Per-thread weight staging slots ->
// no barriers needed in the pipelined loop (each thread consumes only its own copies).
template<int TI, int NJ>
__device__ __forceinline__ void wpass(
    int jb, int ib,
    float* __restrict__ W,
    const float* __restrict__ rowP,  // trace rows   [i][b]
    const float* __restrict__ rowS,  // s_prev rows  [i][b]
    const float* __restrict__ rowC,  // s_cur rows   [i][b]
    const float* __restrict__ colS,  // s_prev cols  [j][b]
    const float* __restrict__ colQ,  // -q cols      [j][b]
    float* __restrict__ cur,         // [j][b]
    float4* sh,                      // row broadcast (reused for epilogue transpose)
    float2* wsh)                     // 2 * 8 * 128 float2 weight stage
{
    const int tid = threadIdx.x;
    const int j0 = jb * 256 + tid * 2;
    const int i0 = ib * TI;
    constexpr int RS = NJ / 2;       // row stride in float2
    constexpr int C = TI / 8;        // chunks

    float2* wgl = (float2*)W + (size_t)i0 * RS + jb * 128 + tid;

    // stage chunks 0 and 1 (per-thread 8B cp.async, fire-and-forget)
    {
        unsigned sd = smem_u32(wsh) + tid * 8;
#pragma unroll
        for (int k = 0; k < 8; k++) cpa8(sd + k * 1024, wgl + (size_t)k * RS);
        cpcommit();
#pragma unroll
        for (int k = 0; k < 8; k++) cpa8(sd + 8192 + k * 1024, wgl + (size_t)(8 + k) * RS);
        cpcommit();
    }

    u64 sA[8], sB[8], qA[8], qB[8], aA[8], aB[8];
    load16(colS + (size_t)j0 * B, sA);
    load16(colS + (size_t)(j0 + 1) * B, sB);
    load16(colQ + (size_t)j0 * B, qA);
    load16(colQ + (size_t)(j0 + 1) * B, qB);
#pragma unroll
    for (int g = 0; g < 8; g++) { aA[g] = 0ull; aB[g] = 0ull; }

    {
        const float4* a0 = (const float4*)(rowP + (size_t)i0 * B);
        const float4* a1 = (const float4*)(rowS + (size_t)i0 * B);
        const float4* a2 = (const float4*)(rowC + (size_t)i0 * B);
#pragma unroll
        for (int k = tid; k < TI * 4; k += 128) {
            sh[k] = a0[k]; sh[TI * 4 + k] = a1[k]; sh[TI * 8 + k] = a2[k];
        }
    }
    __syncthreads();

    const F4U* p4 = (const F4U*)sh;
    const F4U* s4 = (const F4U*)(sh + TI * 4);
    const F4U* c4 = (const F4U*)(sh + TI * 8);

    for (int c = 0; c < C; c++) {
        if (c + 1 < C) asm volatile("cp.async.wait_group 1;" ::: "memory");
        else           asm volatile("cp.async.wait_group 0;" ::: "memory");
        const float2* wsrc = wsh + (c & 1) * 1024 + tid;
#pragma unroll 2
        for (int k = 0; k < 8; k++) {
            int r = c * 8 + k;
            float2 w = wsrc[k * 128];
            u64 dA0 = 0ull, dA1 = 0ull, dB0 = 0ull, dB1 = 0ull;
            F4U v;
#pragma unroll
            for (int g = 0; g < 4; g++) {
                v = p4[r * 4 + g];
                fma2(dA0, v.u[0], sA[2 * g]); fma2(dA1, v.u[1], sA[2 * g + 1]);
                fma2(dB0, v.u[0], sB[2 * g]); fma2(dB1, v.u[1], sB[2 * g + 1]);
            }
#pragma unroll
            for (int g = 0; g < 4; g++) {
                v = s4[r * 4 + g];
                fma2(dA0, v.u[0], qA[2 * g]); fma2(dA1, v.u[1], qA[2 * g + 1]);
                fma2(dB0, v.u[0], qB[2 * g]); fma2(dB1, v.u[1], qB[2 * g + 1]);
            }
            u64 eA = add2(dA0, dA1), eB = add2(dB0, dB1);
            float la, ha, lb, hb;
            unpack2(eA, la, ha); unpack2(eB, lb, hb);
            float nwa = fminf(1.f, fmaxf(-1.f, fmaf(LR, la + ha, w.x)));
            float nwb = fminf(1.f, fmaxf(-1.f, fmaf(LR, lb + hb, w.y)));
            float2 nw; nw.x = nwa; nw.y = nwb;
            wgl[(size_t)r * RS] = nw;
            u64 wa2 = pack2(nwa, nwa), wb2 = pack2(nwb, nwb);
#pragma unroll
            for (int g = 0; g < 4; g++) {
                v = c4[r * 4 + g];
                fma2(aA[2 * g], v.u[0], wa2); fma2(aA[2 * g + 1], v.u[1], wa2);
                fma2(aB[2 * g], v.u[0], wb2); fma2(aB[2 * g + 1], v.u[1], wb2);
            }
        }
        if (c + 2 < C) {
            unsigned sd = smem_u32(wsh) + (c & 1) * 8192 + tid * 8;
            const float2* gs = wgl + (size_t)(c + 2) * 8 * RS;
#pragma unroll
            for (int k = 0; k < 8; k++) cpa8(sd + k * 1024, gs + (size_t)k * RS);
            cpcommit();
        }
    }

    // ---- coalesced reduction epilogue via smem transpose (validated in R9) ----
    __syncthreads();
    float* sT = (float*)sh;
    {
        int lj = tid * 2;
#pragma unroll
        for (int g = 0; g < 8; g++) {
            float lo, hi;
            unpack2(aA[g], lo, hi);
            sT[lj * 17 + 2 * g] = lo; sT[lj * 17 + 2 * g + 1] = hi;
            unpack2(aB[g], lo, hi);
            sT[(lj + 1) * 17 + 2 * g] = lo; sT[(lj + 1) * 17 + 2 * g + 1] = hi;
        }
    }
    __syncthreads();
    {
        float* curb = cur + (size_t)jb * 256 * B;
#pragma unroll
        for (int k = 0; k < 8; k++) {
            int gi = k * 512 + tid * 4;
            int j = gi >> 4, b = gi & 15;
            const float* sp = sT + j * 17 + b;
            red4(curb + gi, sp[0], sp[1], sp[2], sp[3]);
        }
    }
}

// ---------------- merged launch: wa(t+1) || wb(t) ----------------
__global__ __launch_bounds__(128, 4) void k_wab(int t) {
    __shared__ float4 sh[TIA * 12];       // 24 KB (>= 256*17 floats for epilogue)
    __shared__ float2 wsh[2 * 8 * 128];   // 16 KB
    int bx = blockIdx.x;
    if (bx < NBA) {
        int ta = t + 1;
        if (ta >= T) return;
        size_t base = (size_t)ta * N0 * B;
        wpass<TIA, N1>(bx % JBA, bx / JBA, g_Wa,
                       g_p0f + base, g_s0f + base, g_s0f + base + (size_t)N0 * B,
                       g_s1f[(ta & 1) ^ 1], g_q0n, g_cur1, sh, wsh);
    } else {
        if (t < 0) return;
        int b2 = bx - NBA;
        wpass<TIB, N2>(b2 % JBB, b2 / JBB, g_Wb,
                       g_p1, g_s1f[(t & 1) ^ 1], g_s1f[t & 1],
                       g_s2f, g_q1n, g_cur2, sh, wsh);
    }
}

// ---------------- init ----------------
__global__ void k_init() {
    int i = blockIdx.x * blockDim.x + threadIdx.x;
    int n = gridDim.x * blockDim.x;
    for (int k = i; k < N0 * B; k += n) { g_s0f[k] = 0.f; g_p0f[k] = 0.f; g_racc[k] = 0.f; }
    for (int k = i; k < N1 * B; k += n) {
        g_s1f[0][k] = 0.f; g_s1f[1][k] = 0.f; g_q0n[k] = 0.f; g_p1[k] = 0.f;
        g_V1[k] = 0.f; g_r1[k] = 0; g_cur1[k] = 0.f;
    }
    for (int k = i; k < N2 * B; k += n) {
        g_s2f[k] = 0.f; g_q1n[k] = 0.f; g_V2[k] = 0.f; g_r2[k] = 0;
        g_cur2[k] = 0.f; g_cnt[k] = 0.f;
    }
}

// ---------------- encoder GEMM ----------------
__global__ void k_enc(const float* __restrict__ x, const float* __restrict__ Wenc) {
    __shared__ float xs[B][128];
    int i = blockIdx.x * 128 + threadIdx.x;
    int d0 = blockIdx.y * 128;
    for (int k = threadIdx.x; k < B * 128; k += 128) {
        int b = k / 128, dl = k % 128;
        xs[b][dl] = x[b * D + d0 + dl];
    }
    __syncthreads();
    float acc[B];
#pragma unroll
    for (int b = 0; b < B; b++) acc[b] = 0.f;
    for (int dl = 0; dl < 128; dl++) {
        float w = Wenc[(size_t)(d0 + dl) * N0 + i];
#pragma unroll
        for (int b = 0; b < B; b++) acc[b] = fmaf(xs[b][dl], w, acc[b]);
    }
#pragma unroll
    for (int b = 0; b < B; b++) atomicAdd(&g_racc[b * N0 + i], acc[b]);
}

// ---------------- precompute s0/p0 ----------------
__global__ void k_pre(const float* __restrict__ u, const float* __restrict__ benc) {
    int idx = blockIdx.x * blockDim.x + threadIdx.x;
    int i = idx & (N0 - 1), b = idx >> 12;
    float rate = 1.f / (1.f + expf(-(g_racc[b * N0 + i] + benc[i])));
    float V = 0.f, p = 0.f;
    int refr = 0;
    const float* up = u + (size_t)b * T * N0 + i;
    for (int t = 0; t < T; t++) {
        float s_in = (up[(size_t)t * N0] < rate) ? 1.f : 0.f;
        V = DECAY * V + s_in;
        bool spk = (V > THRESH) && (refr <= 0);
        float s = spk ? 1.f : 0.f;
        V = spk ? 0.f : V;
        refr = spk ? 2 : (refr > 0 ? refr - 1 : 0);
        p = TRD * p + s;
        size_t o = (size_t)(t + 1) * N0 * B + (size_t)i * B + b;
        g_s0f[o] = s;
        g_p0f[o] = p;
    }
}

// ---------------- fused LIF: lif1(t) + lif2(t-1), [j][b] flat, coalesced ----------------
__global__ void k_lif12(int t) {
    int g = blockIdx.x * blockDim.x + threadIdx.x; // over N1*B
    // lif1(t)
    float cur = g_cur1[g];
    g_cur1[g] = 0.f;
    float V = DECAY * g_V1[g] + cur;
    int refr = g_r1[g];
    bool spk = (V > THRESH) && (refr <= 0);
    float s = spk ? 1.f : 0.f;
    g_V1[g] = spk ? 0.f : V;
    g_r1[g] = spk ? 2 : (refr > 0 ? refr - 1 : 0);
    g_s1f[t & 1][g] = s;
    g_q0n[g] = TRD * g_q0n[g] - s;
    // lif2(t-1)
    if (t > 0) {
        float s1m = g_s1f[(t & 1) ^ 1][g];
        g_p1[g] = TRD * g_p1[g] + s1m;
        if (g < N2 * B) {
            float c2 = g_cur2[g];
            g_cur2[g] = 0.f;
            float V2 = DECAY * g_V2[g] + c2;
            int r2 = g_r2[g];
            bool sp2 = (V2 > THRESH) && (r2 <= 0);
            float s2 = sp2 ? 1.f : 0.f;
            g_V2[g] = sp2 ? 0.f : V2;
            g_r2[g] = sp2 ? 2 : (r2 > 0 ? r2 - 1 : 0);
            g_cnt[g] += s2;
            g_s2f[g] = s2;
            g_q1n[g] = TRD * g_q1n[g] - s2;
        }
    }
}

// ---------------- final lif2 (step T-1) ----------------
__global__ void k_lif2fin() {
    int g = blockIdx.x * blockDim.x + threadIdx.x; // over N2*B
    float c2 = g_cur2[g];
    float V2 = DECAY * g_V2[g] + c2;
    int r2 = g_r2[g];
    bool sp2 = (V2 > THRESH) && (r2 <= 0);
    g_cnt[g] += sp2 ? 1.f : 0.f;
}

// ---------------- readout (cnt is [j][b]) ----------------
__global__ void k_out(const float* __restrict__ Wdec, const float* __restrict__ bdec,
                      float* __restrict__ out) {
    int b = blockIdx.x;
    int tid = threadIdx.x;
    int lane = tid & 31, wid = tid >> 5;
    float a[NCLS];
#pragma unroll
    for (int c = 0; c < NCLS; c++) a[c] = 0.f;
    for (int k = tid; k < N2; k += 256) {
        float cv = g_cnt[k * B + b];
#pragma unroll
        for (int c = 0; c < NCLS; c++) a[c] = fmaf(cv, Wdec[k * NCLS + c], a[c]);
    }
#pragma unroll
    for (int c = 0; c < NCLS; c++)
#pragma unroll
        for (int o = 16; o > 0; o >>= 1)
            a[c] += __shfl_xor_sync(0xffffffffu, a[c], o);
    __shared__ float sred[8][NCLS];
    if (lane == 0)
#pragma unroll
        for (int c = 0; c < NCLS; c++) sred[wid][c] = a[c];
    __syncthreads();
    if (tid < NCLS) {
        float s = bdec[tid];
#pragma unroll
        for (int w = 0; w < 8; w++) s += sred[w][tid];
        out[b * NCLS + tid] = s;
    }
}

// ---------------- launch ----------------
extern "C" void kernel_launch(void* const* d_in, const int* in_sizes, int n_in,
                              void* d_out, int out_size) {
    (void)in_sizes; (void)n_in; (void)out_size;
    const float* x    = (const float*)d_in[0];
    const float* u    = (const float*)d_in[1];
    const float* Wenc = (const float*)d_in[2];
    const float* benc = (const float*)d_in[3];
    const float* W0   = (const float*)d_in[4];
    const float* W1   = (const float*)d_in[5];
    const float* Wdec = (const float*)d_in[6];
    const float* bdec = (const float*)d_in[7];
    float* out = (float*)d_out;

    cudaMemcpyToSymbolAsync(g_Wa, W0, sizeof(float) * (size_t)N0 * N1, 0,
                            cudaMemcpyDeviceToDevice, 0);
    cudaMemcpyToSymbolAsync(g_Wb, W1, sizeof(float) * (size_t)N1 * N2, 0,
                            cudaMemcpyDeviceToDevice, 0);
    k_init<<<256, 256>>>();
    k_enc<<<dim3(N0 / 128, D / 128), 128>>>(x, Wenc);
    k_pre<<<(N0 * B) / 256, 256>>>(u, benc);
    // k_wab(t) = wa(t+1) || wb(t); lif12(t) between consecutive k_wab calls.
    for (int t = -1; t < T; t++) {
        k_wab<<<NBA + NBB, 128>>>(t);
        if (t + 1 < T) k_lif12<<<(N1 * B) / 256, 256>>>(t + 1);
    }
    k_lif2fin<<<(N2 * B) / 256, 256>>>();
    k_out<<<B, 256>>>(Wdec, bdec, out);
}

// round 15
// speedup vs baseline: 1.1069x; 1.0320x over previous
#include <cuda_runtime.h>
#include <math.h>

#define B    16
#define D    2048
#define T    100
#define N0   4096
#define N1   4096
#define N2   2048
#define NCLS 10

constexpr float DECAY = 0.9f;
constexpr float THRESH = 1.0f;
constexpr float LR = 0.01f;
constexpr float TRD = 0.95f;

#define TIA 64
#define TIB 64
#define JBA (N1 / 256)          // 16 j-blocks for Wa
#define JBB (N2 / 256)          // 8  j-blocks for Wb
#define NBA (JBA * (N0 / TIA))  // 1024 wa tiles
#define NBB (JBB * (N1 / TIB))  // 512 wb tiles

// ---------------- device state (per-neuron state in [j][b] layout, b fast) ----------------
__device__ float g_Wa[(size_t)N0 * N1];           // 64 MB
__device__ float g_Wb[(size_t)N1 * N2];           // 32 MB
__device__ float g_s0f[(size_t)(T + 1) * N0 * B];
__device__ float g_p0f[(size_t)(T + 1) * N0 * B];
__device__ float g_s1f[2][N1 * B];
__device__ float g_s2f[N2 * B];
__device__ float g_q0n[N1 * B];
__device__ float g_q1n[N2 * B];
__device__ float g_p1[N1 * B];
__device__ float g_V1[N1 * B];
__device__ float g_V2[N2 * B];
__device__ int   g_r1[N1 * B];
__device__ int   g_r2[N2 * B];
__device__ float g_cur1[N1 * B];                  // [j][b]
__device__ float g_cur2[N2 * B];                  // [j][b]
__device__ float g_cnt[N2 * B];                   // [j][b]
__device__ float g_racc[B * N0];

// ---------------- helpers ----------------
typedef unsigned long long u64;
union F4U { float4 f4; u64 u[2]; };
__device__ __forceinline__ u64 pack2(float lo, float hi) {
    u64 r; asm("mov.b64 %0, {%1,%2};" : "=l"(r) : "f"(lo), "f"(hi)); return r;
}
__device__ __forceinline__ void unpack2(u64 v, float& lo, float& hi) {
    asm("mov.b64 {%0,%1}, %2;" : "=f"(lo), "=f"(hi) : "l"(v));
}
__device__ __forceinline__ void fma2(u64& acc, u64 a, u64 b) {
    asm("fma.rn.f32x2 %0, %1, %2, %0;" : "+l"(acc) : "l"(a), "l"(b));
}
__device__ __forceinline__ u64 add2(u64 a, u64 b) {
    u64 r; asm("add.rn.f32x2 %0, %1, %2;" : "=l"(r) : "l"(a), "l"(b)); return r;
}
__device__ __forceinline__ void load16(const float* p, u64* dst) {
    const float4* p4 = (const float4*)p;
    F4U v;
#pragma unroll
    for (int q = 0; q < 4; q++) {
        v.f4 = p4[q];
        dst[2 * q] = v.u[0]; dst[2 * q + 1] = v.u[1];
    }
}
__device__ __forceinline__ unsigned smem_u32(const void* p) {
    return (unsigned)__cvta_generic_to_shared(p);
}
__device__ __forceinline__ void cpa8(unsigned sdst, const float2* gsrc) {
    asm volatile("cp.async.ca.shared.global [%0], [%1], 8;" :: "r"(sdst), "l"(gsrc));
}
__device__ __forceinline__ void cpcommit() {
    asm volatile("cp.async.commit_group;" ::: "memory");
}
__device__ __forceinline__ void red4(float* addr, float a, float b, float c, float d) {
    asm volatile("red.global.add.v4.f32 [%0], {%1, %2, %3, %4};"
                 :: "l"(addr), "f"(a), "f"(b), "f"(c), "f"(d) : "memory");
}
__device__ __forceinline__ void pdl_wait() {
    asm volatile("griddepcontrol.wait;" ::: "memory");
}
__device__ __forceinline__ void pdl_launch_dep() {
    asm volatile("griddepcontrol.launch_dependents;" ::: "memory");
}

// ---------------- W-pass: per-thread cp.async-staged weights + fused STDP + GEMM ----------------
// Thread owns adjacent columns (j0, j0+1). Weight staging is issued BEFORE
// griddepcontrol.wait (weights are not written by the preceding lif12 kernel),
// overlapping the predecessor. Everything touching lif outputs comes after the wait.
template<int TI, int NJ>
__device__ __forceinline__ void wpass(
    int jb, int ib,
    float* __restrict__ W,
    const float* __restrict__ rowP,  // trace rows   [i][b]
    const float* __restrict__ rowS,  // s_prev rows  [i][b]
    const float* __restrict__ rowC,  // s_cur rows   [i][b]
    const float* __restrict__ colS,  // s_prev cols  [j][b]
    const float* __restrict__ colQ,  // -q cols      [j][b]
    float* __restrict__ cur,         // [j][b]
    float4* sh,                      // row broadcast + epilogue transpose
    float2* wsh)                     // 2 * 8 * 128 float2 weight stage
{
    const int tid = threadIdx.x;
    const int j0 = jb * 256 + tid * 2;
    const int i0 = ib * TI;
    constexpr int RS = NJ / 2;       // row stride in float2
    constexpr int C = TI / 8;        // chunks

    float2* wgl = (float2*)W + (size_t)i0 * RS + jb * 128 + tid;

    // stage chunks 0 and 1 (per-thread 8B cp.async) — pre-wait, overlaps predecessor
    {
        unsigned sd = smem_u32(wsh) + tid * 8;
#pragma unroll
        for (int k = 0; k < 8; k++) cpa8(sd + k * 1024, wgl + (size_t)k * RS);
        cpcommit();
#pragma unroll
        for (int k = 0; k < 8; k++) cpa8(sd + 8192 + k * 1024, wgl + (size_t)(8 + k) * RS);
        cpcommit();
    }

    pdl_wait();   // predecessor (lif12) fully complete + its writes visible

    u64 sA[8], sB[8], qA[8], qB[8], aA[8], aB[8];
    load16(colS + (size_t)j0 * B, sA);
    load16(colS + (size_t)(j0 + 1) * B, sB);
    load16(colQ + (size_t)j0 * B, qA);
    load16(colQ + (size_t)(j0 + 1) * B, qB);
#pragma unroll
    for (int g = 0; g < 8; g++) { aA[g] = 0ull; aB[g] = 0ull; }

    {
        const float4* a0 = (const float4*)(rowP + (size_t)i0 * B);
        const float4* a1 = (const float4*)(rowS + (size_t)i0 * B);
        const float4* a2 = (const float4*)(rowC + (size_t)i0 * B);
#pragma unroll
        for (int k = tid; k < TI * 4; k += 128) {
            sh[k] = a0[k]; sh[TI * 4 + k] = a1[k]; sh[TI * 8 + k] = a2[k];
        }
    }
    __syncthreads();

    const F4U* p4 = (const F4U*)sh;
    const F4U* s4 = (const F4U*)(sh + TI * 4);
    const F4U* c4 = (const F4U*)(sh + TI * 8);

    for (int c = 0; c < C; c++) {
        if (c + 1 < C) asm volatile("cp.async.wait_group 1;" ::: "memory");
        else           asm volatile("cp.async.wait_group 0;" ::: "memory");
        const float2* wsrc = wsh + (c & 1) * 1024 + tid;
#pragma unroll 2
        for (int k = 0; k < 8; k++) {
            int r = c * 8 + k;
            float2 w = wsrc[k * 128];
            u64 dA0 = 0ull, dA1 = 0ull, dB0 = 0ull, dB1 = 0ull;
            F4U v;
#pragma unroll
            for (int g = 0; g < 4; g++) {
                v = p4[r * 4 + g];
                fma2(dA0, v.u[0], sA[2 * g]); fma2(dA1, v.u[1], sA[2 * g + 1]);
                fma2(dB0, v.u[0], sB[2 * g]); fma2(dB1, v.u[1], sB[2 * g + 1]);
            }
#pragma unroll
            for (int g = 0; g < 4; g++) {
                v = s4[r * 4 + g];
                fma2(dA0, v.u[0], qA[2 * g]); fma2(dA1, v.u[1], qA[2 * g + 1]);
                fma2(dB0, v.u[0], qB[2 * g]); fma2(dB1, v.u[1], qB[2 * g + 1]);
            }
            u64 eA = add2(dA0, dA1), eB = add2(dB0, dB1);
            float la, ha, lb, hb;
            unpack2(eA, la, ha); unpack2(eB, lb, hb);
            float nwa = fminf(1.f, fmaxf(-1.f, fmaf(LR, la + ha, w.x)));
            float nwb = fminf(1.f, fmaxf(-1.f, fmaf(LR, lb + hb, w.y)));
            float2 nw; nw.x = nwa; nw.y = nwb;
            wgl[(size_t)r * RS] = nw;
            u64 wa2 = pack2(nwa, nwa), wb2 = pack2(nwb, nwb);
#pragma unroll
            for (int g = 0; g < 4; g++) {
                v = c4[r * 4 + g];
                fma2(aA[2 * g], v.u[0], wa2); fma2(aA[2 * g + 1], v.u[1], wa2);
                fma2(aB[2 * g], v.u[0], wb2); fma2(aB[2 * g + 1], v.u[1], wb2);
            }
        }
        if (c + 2 < C) {
            unsigned sd = smem_u32(wsh) + (c & 1) * 8192 + tid * 8;
            const float2* gs = wgl + (size_t)(c + 2) * 8 * RS;
#pragma unroll
            for (int k = 0; k < 8; k++) cpa8(sd + k * 1024, gs + (size_t)k * RS);
            cpcommit();
        }
    }

    // ---- coalesced reduction epilogue via smem transpose ----
    __syncthreads();
    float* sT = (float*)sh;
    {
        int lj = tid * 2;
#pragma unroll
        for (int g = 0; g < 8; g++) {
            float lo, hi;
            unpack2(aA[g], lo, hi);
            sT[lj * 17 + 2 * g] = lo; sT[lj * 17 + 2 * g + 1] = hi;
            unpack2(aB[g], lo, hi);
            sT[(lj + 1) * 17 + 2 * g] = lo; sT[(lj + 1) * 17 + 2 * g + 1] = hi;
        }
    }
    __syncthreads();
    {
        float* curb = cur + (size_t)jb * 256 * B;
#pragma unroll
        for (int k = 0; k < 8; k++) {
            int gi = k * 512 + tid * 4;
            int j = gi >> 4, b = gi & 15;
            const float* sp = sT + j * 17 + b;
            red4(curb + gi, sp[0], sp[1], sp[2], sp[3]);
        }
    }
}

// ---------------- merged launch: wa(t+1) || wb(t) ----------------
__global__ __launch_bounds__(128, 4) void k_wab(int t) {
    __shared__ float4 sh[1088];           // 17.4 KB: row stage (TI*12<=768) + epilogue (1088)
    __shared__ float2 wsh[2 * 8 * 128];   // 16 KB
    int bx = blockIdx.x;
    if (bx < NBA) {
        int ta = t + 1;
        if (ta >= T) return;
        size_t base = (size_t)ta * N0 * B;
        wpass<TIA, N1>(bx % JBA, bx / JBA, g_Wa,
                       g_p0f + base, g_s0f + base, g_s0f + base + (size_t)N0 * B,
                       g_s1f[(ta & 1) ^ 1], g_q0n, g_cur1, sh, wsh);
    } else {
        if (t < 0) return;
        int b2 = bx - NBA;
        wpass<TIB, N2>(b2 % JBB, b2 / JBB, g_Wb,
                       g_p1, g_s1f[(t & 1) ^ 1], g_s1f[t & 1],
                       g_s2f, g_q1n, g_cur2, sh, wsh);
    }
}

// ---------------- init ----------------
__global__ void k_init() {
    int i = blockIdx.x * blockDim.x + threadIdx.x;
    int n = gridDim.x * blockDim.x;
    for (int k = i; k < N0 * B; k += n) { g_s0f[k] = 0.f; g_p0f[k] = 0.f; g_racc[k] = 0.f; }
    for (int k = i; k < N1 * B; k += n) {
        g_s1f[0][k] = 0.f; g_s1f[1][k] = 0.f; g_q0n[k] = 0.f; g_p1[k] = 0.f;
        g_V1[k] = 0.f; g_r1[k] = 0; g_cur1[k] = 0.f;
    }
    for (int k = i; k < N2 * B; k += n) {
        g_s2f[k] = 0.f; g_q1n[k] = 0.f; g_V2[k] = 0.f; g_r2[k] = 0;
        g_cur2[k] = 0.f; g_cnt[k] = 0.f;
    }
}

// ---------------- encoder GEMM ----------------
__global__ void k_enc(const float* __restrict__ x, const float* __restrict__ Wenc) {
    __shared__ float xs[B][128];
    int i = blockIdx.x * 128 + threadIdx.x;
    int d0 = blockIdx.y * 128;
    for (int k = threadIdx.x; k < B * 128; k += 128) {
        int b = k / 128, dl = k % 128;
        xs[b][dl] = x[b * D + d0 + dl];
    }
    __syncthreads();
    float acc[B];
#pragma unroll
    for (int b = 0; b < B; b++) acc[b] = 0.f;
    for (int dl = 0; dl < 128; dl++) {
        float w = Wenc[(size_t)(d0 + dl) * N0 + i];
#pragma unroll
        for (int b = 0; b < B; b++) acc[b] = fmaf(xs[b][dl], w, acc[b]);
    }
#pragma unroll
    for (int b = 0; b < B; b++) atomicAdd(&g_racc[b * N0 + i], acc[b]);
}

// ---------------- precompute s0/p0 ----------------
__global__ void k_pre(const float* __restrict__ u, const float* __restrict__ benc) {
    int idx = blockIdx.x * blockDim.x + threadIdx.x;
    int i = idx & (N0 - 1), b = idx >> 12;
    float rate = 1.f / (1.f + expf(-(g_racc[b * N0 + i] + benc[i])));
    float V = 0.f, p = 0.f;
    int refr = 0;
    const float* up = u + (size_t)b * T * N0 + i;
    for (int t = 0; t < T; t++) {
        float s_in = (up[(size_t)t * N0] < rate) ? 1.f : 0.f;
        V = DECAY * V + s_in;
        bool spk = (V > THRESH) && (refr <= 0);
        float s = spk ? 1.f : 0.f;
        V = spk ? 0.f : V;
        refr = spk ? 2 : (refr > 0 ? refr - 1 : 0);
        p = TRD * p + s;
        size_t o = (size_t)(t + 1) * N0 * B + (size_t)i * B + b;
        g_s0f[o] = s;
        g_p0f[o] = p;
    }
}

// ---------------- fused LIF: lif1(t) + lif2(t-1), [j][b] flat, coalesced ----------------
// PDL: wait for wab(t-phase) completion, then IMMEDIATELY allow the next k_wab to
// launch and run its (weight-only) prologue concurrently with this body.
__global__ void k_lif12(int t) {
    pdl_wait();
    pdl_launch_dep();
    int g = blockIdx.x * blockDim.x + threadIdx.x; // over N1*B
    // lif1(t)
    float cur = g_cur1[g];
    g_cur1[g] = 0.f;
    float V = DECAY * g_V1[g] + cur;
    int refr = g_r1[g];
    bool spk = (V > THRESH) && (refr <= 0);
    float s = spk ? 1.f : 0.f;
    g_V1[g] = spk ? 0.f : V;
    g_r1[g] = spk ? 2 : (refr > 0 ? refr - 1 : 0);
    g_s1f[t & 1][g] = s;
    g_q0n[g] = TRD * g_q0n[g] - s;
    // lif2(t-1)
    if (t > 0) {
        float s1m = g_s1f[(t & 1) ^ 1][g];
        g_p1[g] = TRD * g_p1[g] + s1m;
        if (g < N2 * B) {
            float c2 = g_cur2[g];
            g_cur2[g] = 0.f;
            float V2 = DECAY * g_V2[g] + c2;
            int r2 = g_r2[g];
            bool sp2 = (V2 > THRESH) && (r2 <= 0);
            float s2 = sp2 ? 1.f : 0.f;
            g_V2[g] = sp2 ? 0.f : V2;
            g_r2[g] = sp2 ? 2 : (r2 > 0 ? r2 - 1 : 0);
            g_cnt[g] += s2;
            g_s2f[g] = s2;
            g_q1n[g] = TRD * g_q1n[g] - s2;
        }
    }
}

// ---------------- final lif2 (step T-1) ----------------
__global__ void k_lif2fin() {
    int g = blockIdx.x * blockDim.x + threadIdx.x; // over N2*B
    float c2 = g_cur2[g];
    float V2 = DECAY * g_V2[g] + c2;
    int r2 = g_r2[g];
    bool sp2 = (V2 > THRESH) && (r2 <= 0);
    g_cnt[g] += sp2 ? 1.f : 0.f;
}

// ---------------- readout (cnt is [j][b]) ----------------
__global__ void k_out(const float* __restrict__ Wdec, const float* __restrict__ bdec,
                      float* __restrict__ out) {
    int b = blockIdx.x;
    int tid = threadIdx.x;
    int lane = tid & 31, wid = tid >> 5;
    float a[NCLS];
#pragma unroll
    for (int c = 0; c < NCLS; c++) a[c] = 0.f;
    for (int k = tid; k < N2; k += 256) {
        float cv = g_cnt[k * B + b];
#pragma unroll
        for (int c = 0; c < NCLS; c++) a[c] = fmaf(cv, Wdec[k * NCLS + c], a[c]);
    }
#pragma unroll
    for (int c = 0; c < NCLS; c++)
#pragma unroll
        for (int o = 16; o > 0; o >>= 1)
            a[c] += __shfl_xor_sync(0xffffffffu, a[c], o);
    __shared__ float sred[8][NCLS];
    if (lane == 0)
#pragma unroll
        for (int c = 0; c < NCLS; c++) sred[wid][c] = a[c];
    __syncthreads();
    if (tid < NCLS) {
        float s = bdec[tid];
#pragma unroll
        for (int w = 0; w < 8; w++) s += sred[w][tid];
        out[b * NCLS + tid] = s;
    }
}

// ---------------- launch ----------------
static void launch_pdl_wab(int t) {
    cudaLaunchConfig_t cfg = {};
    cfg.gridDim = dim3(NBA + NBB, 1, 1);
    cfg.blockDim = dim3(128, 1, 1);
    cfg.dynamicSmemBytes = 0;
    cfg.stream = 0;
    cudaLaunchAttribute at[1];
    at[0].id = cudaLaunchAttributeProgrammaticStreamSerialization;
    at[0].val.programmaticStreamSerializationAllowed = 1;
    cfg.attrs = at;
    cfg.numAttrs = 1;
    cudaLaunchKernelEx(&cfg, k_wab, t);
}

static void launch_pdl_lif(int t) {
    cudaLaunchConfig_t cfg = {};
    cfg.gridDim = dim3((N1 * B) / 256, 1, 1);
    cfg.blockDim = dim3(256, 1, 1);
    cfg.dynamicSmemBytes = 0;
    cfg.stream = 0;
    cudaLaunchAttribute at[1];
    at[0].id = cudaLaunchAttributeProgrammaticStreamSerialization;
    at[0].val.programmaticStreamSerializationAllowed = 1;
    cfg.attrs = at;
    cfg.numAttrs = 1;
    cudaLaunchKernelEx(&cfg, k_lif12, t);
}

extern "C" void kernel_launch(void* const* d_in, const int* in_sizes, int n_in,
                              void* d_out, int out_size) {
    (void)in_sizes; (void)n_in; (void)out_size;
    const float* x    = (const float*)d_in[0];
    const float* u    = (const float*)d_in[1];
    const float* Wenc = (const float*)d_in[2];
    const float* benc = (const float*)d_in[3];
    const float* W0   = (const float*)d_in[4];
    const float* W1   = (const float*)d_in[5];
    const float* Wdec = (const float*)d_in[6];
    const float* bdec = (const float*)d_in[7];
    float* out = (float*)d_out;

    cudaMemcpyToSymbolAsync(g_Wa, W0, sizeof(float) * (size_t)N0 * N1, 0,
                            cudaMemcpyDeviceToDevice, 0);
    cudaMemcpyToSymbolAsync(g_Wb, W1, sizeof(float) * (size_t)N1 * N2, 0,
                            cudaMemcpyDeviceToDevice, 0);
    k_init<<<256, 256>>>();
    k_enc<<<dim3(N0 / 128, D / 128), 128>>>(x, Wenc);
    k_pre<<<(N0 * B) / 256, 256>>>(u, benc);
    // k_wab(t) = wa(t+1) || wb(t); lif12(t) between consecutive k_wab calls.
    for (int t = -1; t < T; t++) {
        launch_pdl_wab(t);
        if (t + 1 < T) launch_pdl_lif(t + 1);
    }
    k_lif2fin<<<(N2 * B) / 256, 256>>>();
    k_out<<<B, 256>>>(Wdec, bdec, out);
}